// round 1
// baseline (speedup 1.0000x reference)
#include <cuda_runtime.h>
#include <math.h>

// DeformAttn: fused 1x1-conv projections + per-pixel 9-sample attention.
// Shapes: q[4,128,128,128], kv[4,128,9,16384], W*[128,128], b*[128]
// out[4,128,128,128] fp32.

namespace {
constexpr int Bn = 4;
constexpr int Cn = 128;       // IN_C == OUT_C
constexpr int Sn = 9;         // n_samples
constexpr int Dn = 16384;     // FH*FW
constexpr int TILE_D = 64;
constexpr int NTHREADS = 256;
constexpr float ATT_SCALE = 0.25f;   // HEAD_C^-0.5, HEAD_C=16

// shared memory layout (in floats)
constexpr int XS_OFF   = 0;            // x tile   [128][64]
constexpr int WT_OFF   = 8192;         // W^T      [128][132] (pad for banks)
constexpr int PART_OFF = 25088;        // logit partials [4][512]
constexpr int WSM_OFF  = 27136;        // exp weights    [512]  (8 heads x 64 d)
constexpr int LSM_OFF  = 27648;        // softmax denom  [512]
constexpr int SMEM_FLOATS = 28160;     // 112,640 bytes
}

__device__ __forceinline__ void load_tile(float* xs, const float* __restrict__ src,
                                          int cstride, int tid) {
    const int dd = tid & 63;
    const int cb = tid >> 6;   // 0..3
#pragma unroll
    for (int r = 0; r < 32; r++) {
        const int c = r * 4 + cb;
        xs[c * 64 + dd] = src[(long)c * cstride + dd];
    }
}

__device__ __forceinline__ void load_wt(float* wt, const float* __restrict__ W, int tid) {
    const int c  = tid & 127;
    const int ob = tid >> 7;   // 0..1
#pragma unroll
    for (int r = 0; r < 64; r++) {
        const int o = r * 2 + ob;
        wt[c * 132 + o] = W[o * 128 + c];   // transpose: wt[c][o]
    }
}

// r[i][j] = bias[o0+i] + sum_c W[o0+i][c] * x[c][d0+j]
__device__ __forceinline__ void gemm_tile(const float* wt, const float* xs,
                                          int o0, int d0,
                                          const float* __restrict__ bias,
                                          float r[4][8]) {
#pragma unroll
    for (int i = 0; i < 4; i++) {
        const float bi = __ldg(&bias[o0 + i]);
#pragma unroll
        for (int j = 0; j < 8; j++) r[i][j] = bi;
    }
#pragma unroll 8
    for (int c = 0; c < 128; c++) {
        const float4 w4 = *reinterpret_cast<const float4*>(wt + c * 132 + o0);
        const float4 xa = *reinterpret_cast<const float4*>(xs + c * 64 + d0);
        const float4 xb = *reinterpret_cast<const float4*>(xs + c * 64 + d0 + 4);
        const float wv[4] = {w4.x, w4.y, w4.z, w4.w};
        const float xv[8] = {xa.x, xa.y, xa.z, xa.w, xb.x, xb.y, xb.z, xb.w};
#pragma unroll
        for (int i = 0; i < 4; i++)
#pragma unroll
            for (int j = 0; j < 8; j++)
                r[i][j] = fmaf(wv[i], xv[j], r[i][j]);
    }
}

__global__ void __launch_bounds__(NTHREADS)
deform_attn_kernel(const float* __restrict__ q,  const float* __restrict__ kv,
                   const float* __restrict__ Wq, const float* __restrict__ bq,
                   const float* __restrict__ Wk, const float* __restrict__ bk,
                   const float* __restrict__ Wv, const float* __restrict__ bv,
                   float* __restrict__ out)
{
    extern __shared__ float sm[];
    float* xs   = sm + XS_OFF;
    float* wt   = sm + WT_OFF;
    float* part = sm + PART_OFF;
    float* wsm  = sm + WSM_OFF;
    float* lsm  = sm + LSM_OFF;

    const int tid = threadIdx.x;
    const int b   = blockIdx.y;
    const int dt  = blockIdx.x * TILE_D;

    const int dg = tid & 7;        // pixel group: d0..d0+7
    const int og = tid >> 3;       // out-channel group (0..31): o0..o0+3
    const int o0 = og * 4;
    const int d0 = dg * 8;
    const int h  = og >> 2;        // head = o0/16
    const int qi = og & 3;         // which of 4 channel-quads within the head

    // ---- Q projection: qp stays in registers for the whole kernel ----
    load_tile(xs, q + (long)b * Cn * Dn + dt, Dn, tid);
    load_wt(wt, Wq, tid);
    lsm[tid] = 0.0f;
    lsm[tid + 256] = 0.0f;
    __syncthreads();

    float qp[4][8];
    gemm_tile(wt, xs, o0, d0, bq, qp);

    float acc[4][8];
#pragma unroll
    for (int i = 0; i < 4; i++)
#pragma unroll
        for (int j = 0; j < 8; j++) acc[i][j] = 0.0f;

    // ---- stream over the 9 samples; kv read exactly once ----
    for (int s = 0; s < Sn; s++) {
        __syncthreads();   // previous readers of xs/wt are done
        load_tile(xs, kv + ((long)b * Cn * Sn + s) * Dn + dt, Sn * Dn, tid);
        load_wt(wt, Wk, tid);
        __syncthreads();

        float kp[4][8];
        gemm_tile(wt, xs, o0, d0, bk, kp);

        // logit partials: this thread's 4 channels lie in one head
#pragma unroll
        for (int j = 0; j < 8; j++) {
            const float p = fmaf(qp[0][j], kp[0][j],
                           fmaf(qp[1][j], kp[1][j],
                           fmaf(qp[2][j], kp[2][j], qp[3][j] * kp[3][j])));
            part[qi * 512 + h * 64 + d0 + j] = p;
        }
        __syncthreads();

        // unnormalized softmax weight (no max-subtraction: logits ~ N(0,1))
        {
            const int i0 = tid, i1 = tid + 256;
            const float l0 = part[i0] + part[512 + i0] + part[1024 + i0] + part[1536 + i0];
            const float w0 = __expf(ATT_SCALE * l0);
            wsm[i0] = w0; lsm[i0] += w0;
            const float l1 = part[i1] + part[512 + i1] + part[1024 + i1] + part[1536 + i1];
            const float w1 = __expf(ATT_SCALE * l1);
            wsm[i1] = w1; lsm[i1] += w1;
        }

        load_wt(wt, Wv, tid);       // xs (kv tile) is reused for V projection
        __syncthreads();

        float vp[4][8];
        gemm_tile(wt, xs, o0, d0, bv, vp);

        float w8[8];
#pragma unroll
        for (int j = 0; j < 8; j++) w8[j] = wsm[h * 64 + d0 + j];
#pragma unroll
        for (int i = 0; i < 4; i++)
#pragma unroll
            for (int j = 0; j < 8; j++)
                acc[i][j] = fmaf(w8[j], vp[i][j], acc[i][j]);
    }

    __syncthreads();
    float linv[8];
#pragma unroll
    for (int j = 0; j < 8; j++) linv[j] = 1.0f / lsm[h * 64 + d0 + j];

#pragma unroll
    for (int i = 0; i < 4; i++) {
        float4 v0 = make_float4(acc[i][0] * linv[0], acc[i][1] * linv[1],
                                acc[i][2] * linv[2], acc[i][3] * linv[3]);
        float4 v1 = make_float4(acc[i][4] * linv[4], acc[i][5] * linv[5],
                                acc[i][6] * linv[6], acc[i][7] * linv[7]);
        float* dst = out + ((long)b * Cn + (o0 + i)) * Dn + dt + d0;
        *reinterpret_cast<float4*>(dst)     = v0;
        *reinterpret_cast<float4*>(dst + 4) = v1;
    }
}

extern "C" void kernel_launch(void* const* d_in, const int* in_sizes, int n_in,
                              void* d_out, int out_size) {
    const float* q  = (const float*)d_in[0];
    const float* kv = (const float*)d_in[1];
    const float* Wq = (const float*)d_in[2];
    const float* bq = (const float*)d_in[3];
    const float* Wk = (const float*)d_in[4];
    const float* bk = (const float*)d_in[5];
    const float* Wv = (const float*)d_in[6];
    const float* bv = (const float*)d_in[7];
    float* out = (float*)d_out;

    const size_t smem = SMEM_FLOATS * sizeof(float);
    cudaFuncSetAttribute(deform_attn_kernel,
                         cudaFuncAttributeMaxDynamicSharedMemorySize, (int)smem);
    dim3 grid(Dn / TILE_D, Bn);   // 256 x 4 = 1024 blocks
    deform_attn_kernel<<<grid, NTHREADS, smem>>>(q, kv, Wq, bq, Wk, bk, Wv, bv, out);
}

// round 3
// speedup vs baseline: 8.9760x; 8.9760x over previous
#include <cuda_runtime.h>
#include <cuda_fp16.h>
#include <cstdint>
#include <math.h>

// DeformAttn via ldmatrix + mma.sync (m16n8k16 fp16, fp32 accum) — base sm_103 ISA.
// out[b,o,d] = softmax_s( (Wq q + bq)·(Wk kv_s + bk) * 0.25 ) · (Wv kv_s + bv)

namespace {
constexpr int Bn = 4, Cn = 128, Sn = 9, Dn = 16384;
constexpr int D_TILE = 64;
constexpr int NT = 256;
constexpr float ATT_SCALE = 0.25f;

// smem byte offsets
constexpr int SM_WQ = 0;           // 128x128 fp16 swizzled, 32KB
constexpr int SM_WK = 32768;
constexpr int SM_WV = 65536;
constexpr int SM_X0 = 98304;       // x tile [128c][64d] fp16, 16KB
constexpr int SM_X1 = 114688;
constexpr int SM_TOTAL = 131072;   // 128KB
}

__device__ __forceinline__ uint32_t smem_u32(const void* p) {
    uint32_t a;
    asm("{ .reg .u64 t; cvta.to.shared.u64 t, %1; cvt.u32.u64 %0, t; }" : "=r"(a) : "l"(p));
    return a;
}

// W buffer: row = out-channel o (256B = 16 chunks of 16B), xor-swizzled
__device__ __forceinline__ uint32_t swzW(int row, int colh) {
    int chunk = (colh >> 3) ^ (row & 7);
    return (uint32_t)(row * 256 + chunk * 16 + (colh & 7) * 2);
}
// x buffer: row = in-channel c (128B = 8 chunks), xor-swizzled
__device__ __forceinline__ uint32_t swzX(int row, int colh) {
    int chunk = (colh >> 3) ^ (row & 7);
    return (uint32_t)(row * 128 + chunk * 16 + (colh & 7) * 2);
}

__device__ __forceinline__ void ldsm4(uint32_t r[4], uint32_t addr) {
    asm volatile("ldmatrix.sync.aligned.m8n8.x4.shared.b16 {%0,%1,%2,%3}, [%4];"
                 : "=r"(r[0]), "=r"(r[1]), "=r"(r[2]), "=r"(r[3]) : "r"(addr));
}
__device__ __forceinline__ void ldsm4t(uint32_t r[4], uint32_t addr) {
    asm volatile("ldmatrix.sync.aligned.m8n8.x4.trans.shared.b16 {%0,%1,%2,%3}, [%4];"
                 : "=r"(r[0]), "=r"(r[1]), "=r"(r[2]), "=r"(r[3]) : "r"(addr));
}
__device__ __forceinline__ void mma16816(float d[4], const uint32_t a[4], const uint32_t b[2]) {
    asm volatile(
        "mma.sync.aligned.m16n8k16.row.col.f32.f16.f16.f32 "
        "{%0,%1,%2,%3},{%4,%5,%6,%7},{%8,%9},{%0,%1,%2,%3};"
        : "+f"(d[0]), "+f"(d[1]), "+f"(d[2]), "+f"(d[3])
        : "r"(a[0]), "r"(a[1]), "r"(a[2]), "r"(a[3]), "r"(b[0]), "r"(b[1]));
}

// convert W [o][c] fp32 row-major -> swizzled fp16 smem
__device__ __forceinline__ void load_w(char* wb, const float* __restrict__ W, int tid) {
#pragma unroll
    for (int i = 0; i < 16; i++) {
        const int g = i * 256 + tid;
        const int o = g >> 5, f4 = g & 31;
        const float4 v = *reinterpret_cast<const float4*>(W + o * 128 + f4 * 4);
        const uint32_t off = swzW(o, f4 * 4);
        *reinterpret_cast<__half2*>(wb + off)     = __floats2half2_rn(v.x, v.y);
        *reinterpret_cast<__half2*>(wb + off + 4) = __floats2half2_rn(v.z, v.w);
    }
}

__device__ __forceinline__ void pf_load(float4 pf[8], const float* __restrict__ src,
                                        long cstride, int tid) {
#pragma unroll
    for (int i = 0; i < 8; i++) {
        const int g = i * 256 + tid;
        const int c = g >> 4, d4 = (g & 15) * 4;
        pf[i] = *reinterpret_cast<const float4*>(src + (long)c * cstride + d4);
    }
}
__device__ __forceinline__ void pf_store(char* xb, const float4 pf[8], int tid) {
#pragma unroll
    for (int i = 0; i < 8; i++) {
        const int g = i * 256 + tid;
        const int c = g >> 4, d4 = (g & 15) * 4;
        const uint32_t off = swzX(c, d4);
        *reinterpret_cast<__half2*>(xb + off)     = __floats2half2_rn(pf[i].x, pf[i].y);
        *reinterpret_cast<__half2*>(xb + off + 4) = __floats2half2_rn(pf[i].z, pf[i].w);
    }
}

// per-warp GEMM: acc[t][n][i] = sum_c W[o][c] x[c][d], warp covers 32 o x 32 d
__device__ __forceinline__ void proj(uint32_t wb, uint32_t xb, int warp_m, int warp_n,
                                     int lane, float acc[2][4][4]) {
#pragma unroll
    for (int t = 0; t < 2; t++)
#pragma unroll
        for (int n = 0; n < 4; n++)
#pragma unroll
            for (int i = 0; i < 4; i++) acc[t][n][i] = 0.0f;

#pragma unroll
    for (int ks = 0; ks < 8; ks++) {
        const int c0 = ks * 16;
        uint32_t a[2][4];
#pragma unroll
        for (int t = 0; t < 2; t++) {
            const int row = warp_m * 32 + t * 16 + (lane & 7) + ((lane >> 3) & 1) * 8;
            const int colh = c0 + (lane >> 4) * 8;
            ldsm4(a[t], wb + swzW(row, colh));
        }
        uint32_t bf[4][2];
#pragma unroll
        for (int np = 0; np < 2; np++) {
            const int tl = lane >> 3;
            const int c = c0 + (tl & 1) * 8 + (lane & 7);
            const int d = warp_n * 32 + np * 16 + (tl >> 1) * 8;
            uint32_t r4[4];
            ldsm4t(r4, xb + swzX(c, d));
            bf[np * 2][0] = r4[0]; bf[np * 2][1] = r4[1];
            bf[np * 2 + 1][0] = r4[2]; bf[np * 2 + 1][1] = r4[3];
        }
#pragma unroll
        for (int t = 0; t < 2; t++)
#pragma unroll
            for (int n = 0; n < 4; n++) mma16816(acc[t][n], a[t], bf[n]);
    }
}

__global__ void __launch_bounds__(NT, 1)
deform_attn_hmma(const float* __restrict__ q,  const float* __restrict__ kv,
                 const float* __restrict__ Wq, const float* __restrict__ bq,
                 const float* __restrict__ Wk, const float* __restrict__ bk,
                 const float* __restrict__ Wv, const float* __restrict__ bv,
                 float* __restrict__ out)
{
    extern __shared__ char smem[];
    const uint32_t sb = smem_u32(smem);
    const int tid = threadIdx.x, lane = tid & 31, wid = tid >> 5;
    const int warp_m = wid & 3, warp_n = wid >> 2;
    const int b = blockIdx.y;
    const int dt = blockIdx.x * D_TILE;

    load_w(smem + SM_WQ, Wq, tid);
    load_w(smem + SM_WK, Wk, tid);
    load_w(smem + SM_WV, Wv, tid);
    {
        float4 pf[8];
        pf_load(pf, q + (long)b * Cn * Dn + dt, (long)Dn, tid);
        pf_store(smem + SM_X0, pf, tid);
    }
    __syncthreads();

    // ---- Q projection (stays in registers) ----
    float qp[2][4][4];
    proj(sb + SM_WQ, sb + SM_X0, warp_m, warp_n, lane, qp);

    const int r0 = warp_m * 32 + (lane >> 2);
    const float bqr[4] = {bq[r0], bq[r0 + 8], bq[r0 + 16], bq[r0 + 24]};
    const float bkr[4] = {bk[r0], bk[r0 + 8], bk[r0 + 16], bk[r0 + 24]};
    const float bvr[4] = {bv[r0], bv[r0 + 8], bv[r0 + 16], bv[r0 + 24]};
#pragma unroll
    for (int t = 0; t < 2; t++)
#pragma unroll
        for (int n = 0; n < 4; n++) {
            qp[t][n][0] += bqr[t * 2];     qp[t][n][1] += bqr[t * 2];
            qp[t][n][2] += bqr[t * 2 + 1]; qp[t][n][3] += bqr[t * 2 + 1];
        }

    float acc[2][4][4], den[2][4][2];
#pragma unroll
    for (int t = 0; t < 2; t++)
#pragma unroll
        for (int n = 0; n < 4; n++) {
            acc[t][n][0] = acc[t][n][1] = acc[t][n][2] = acc[t][n][3] = 0.0f;
            den[t][n][0] = den[t][n][1] = 0.0f;
        }

    // prime sample 0 into X0 (after Q-proj consumers are done)
    __syncthreads();
    {
        float4 pf[8];
        pf_load(pf, kv + (long)(b * Cn) * Sn * Dn + dt, (long)Sn * Dn, tid);
        pf_store(smem + SM_X0, pf, tid);
    }
    __syncthreads();

    float4 pf[8];
    for (int s = 0; s < Sn; s++) {
        const uint32_t xb = sb + ((s & 1) ? SM_X1 : SM_X0);
        if (s + 1 < Sn)
            pf_load(pf, kv + ((long)(b * Cn) * Sn + (s + 1)) * Dn + dt, (long)Sn * Dn, tid);

        // K projection -> logits -> softmax weights
        float kp[2][4][4];
        proj(sb + SM_WK, xb, warp_m, warp_n, lane, kp);
        float w[2][4][2];
#pragma unroll
        for (int t = 0; t < 2; t++)
#pragma unroll
            for (int n = 0; n < 4; n++) {
                float pe = qp[t][n][0] * (kp[t][n][0] + bkr[t * 2]) +
                           qp[t][n][2] * (kp[t][n][2] + bkr[t * 2 + 1]);
                float po = qp[t][n][1] * (kp[t][n][1] + bkr[t * 2]) +
                           qp[t][n][3] * (kp[t][n][3] + bkr[t * 2 + 1]);
                pe += __shfl_xor_sync(0xffffffffu, pe, 4);
                pe += __shfl_xor_sync(0xffffffffu, pe, 8);
                pe += __shfl_xor_sync(0xffffffffu, pe, 16);
                po += __shfl_xor_sync(0xffffffffu, po, 4);
                po += __shfl_xor_sync(0xffffffffu, po, 8);
                po += __shfl_xor_sync(0xffffffffu, po, 16);
                const float we = __expf(ATT_SCALE * pe);
                const float wo = __expf(ATT_SCALE * po);
                w[t][n][0] = we; w[t][n][1] = wo;
                den[t][n][0] += we; den[t][n][1] += wo;
            }

        // V projection -> weighted accumulate
        float vp[2][4][4];
        proj(sb + SM_WV, xb, warp_m, warp_n, lane, vp);
#pragma unroll
        for (int t = 0; t < 2; t++)
#pragma unroll
            for (int n = 0; n < 4; n++) {
                acc[t][n][0] = fmaf(w[t][n][0], vp[t][n][0] + bvr[t * 2],     acc[t][n][0]);
                acc[t][n][1] = fmaf(w[t][n][1], vp[t][n][1] + bvr[t * 2],     acc[t][n][1]);
                acc[t][n][2] = fmaf(w[t][n][0], vp[t][n][2] + bvr[t * 2 + 1], acc[t][n][2]);
                acc[t][n][3] = fmaf(w[t][n][1], vp[t][n][3] + bvr[t * 2 + 1], acc[t][n][3]);
            }

        __syncthreads();   // everyone done reading buffers from iters s-1 and s
        if (s + 1 < Sn) {
            pf_store(smem + (((s + 1) & 1) ? SM_X1 : SM_X0), pf, tid);
            __syncthreads();
        }
    }

    // ---- output ----
#pragma unroll
    for (int t = 0; t < 2; t++)
#pragma unroll
        for (int n = 0; n < 4; n++) {
            const int row = warp_m * 32 + t * 16 + (lane >> 2);
            float* dst = out + ((long)(b * Cn + row)) * Dn + dt + warp_n * 32 + n * 8 + (lane & 3) * 2;
            const float de = den[t][n][0], dz = den[t][n][1];
            float2 v0 = make_float2(acc[t][n][0] / de, acc[t][n][1] / dz);
            float2 v1 = make_float2(acc[t][n][2] / de, acc[t][n][3] / dz);
            *reinterpret_cast<float2*>(dst) = v0;
            *reinterpret_cast<float2*>(dst + (long)8 * Dn) = v1;
        }
}

extern "C" void kernel_launch(void* const* d_in, const int* in_sizes, int n_in,
                              void* d_out, int out_size) {
    const float* q  = (const float*)d_in[0];
    const float* kv = (const float*)d_in[1];
    const float* Wq = (const float*)d_in[2];
    const float* bq = (const float*)d_in[3];
    const float* Wk = (const float*)d_in[4];
    const float* bk = (const float*)d_in[5];
    const float* Wv = (const float*)d_in[6];
    const float* bv = (const float*)d_in[7];
    float* out = (float*)d_out;

    cudaFuncSetAttribute(deform_attn_hmma,
                         cudaFuncAttributeMaxDynamicSharedMemorySize, SM_TOTAL);
    dim3 grid(Dn / D_TILE, Bn);   // 256 x 4
    deform_attn_hmma<<<grid, NT, SM_TOTAL>>>(q, kv, Wq, bq, Wk, bk, Wv, bv, out);
}

// round 4
// speedup vs baseline: 9.9682x; 1.1105x over previous
#include <cuda_runtime.h>
#include <cuda_fp16.h>
#include <cstdint>
#include <math.h>

// DeformAttn via ldmatrix + mma.sync (m16n8k16 fp16, fp32 accum) — base sm_103 ISA.
// Round 4: fused K+V projection sharing B fragments; bk dropped (softmax-invariant),
// bv hoisted out of the sample loop (softmax weights sum to 1).

namespace {
constexpr int Bn = 4, Cn = 128, Sn = 9, Dn = 16384;
constexpr int D_TILE = 64;
constexpr int NT = 256;
constexpr float ATT_SCALE = 0.25f;

constexpr int SM_WQ = 0;           // 128x128 fp16 swizzled, 32KB each
constexpr int SM_WK = 32768;
constexpr int SM_WV = 65536;
constexpr int SM_X0 = 98304;       // x tile [128c][64d] fp16, 16KB
constexpr int SM_X1 = 114688;
constexpr int SM_TOTAL = 131072;
}

__device__ __forceinline__ uint32_t smem_u32(const void* p) {
    uint32_t a;
    asm("{ .reg .u64 t; cvta.to.shared.u64 t, %1; cvt.u32.u64 %0, t; }" : "=r"(a) : "l"(p));
    return a;
}
__device__ __forceinline__ uint32_t swzW(int row, int colh) {
    int chunk = (colh >> 3) ^ (row & 7);
    return (uint32_t)(row * 256 + chunk * 16 + (colh & 7) * 2);
}
__device__ __forceinline__ uint32_t swzX(int row, int colh) {
    int chunk = (colh >> 3) ^ (row & 7);
    return (uint32_t)(row * 128 + chunk * 16 + (colh & 7) * 2);
}
__device__ __forceinline__ void ldsm4(uint32_t r[4], uint32_t addr) {
    asm volatile("ldmatrix.sync.aligned.m8n8.x4.shared.b16 {%0,%1,%2,%3}, [%4];"
                 : "=r"(r[0]), "=r"(r[1]), "=r"(r[2]), "=r"(r[3]) : "r"(addr));
}
__device__ __forceinline__ void ldsm4t(uint32_t r[4], uint32_t addr) {
    asm volatile("ldmatrix.sync.aligned.m8n8.x4.trans.shared.b16 {%0,%1,%2,%3}, [%4];"
                 : "=r"(r[0]), "=r"(r[1]), "=r"(r[2]), "=r"(r[3]) : "r"(addr));
}
__device__ __forceinline__ void mma16816(float d[4], const uint32_t a[4], const uint32_t b[2]) {
    asm volatile(
        "mma.sync.aligned.m16n8k16.row.col.f32.f16.f16.f32 "
        "{%0,%1,%2,%3},{%4,%5,%6,%7},{%8,%9},{%0,%1,%2,%3};"
        : "+f"(d[0]), "+f"(d[1]), "+f"(d[2]), "+f"(d[3])
        : "r"(a[0]), "r"(a[1]), "r"(a[2]), "r"(a[3]), "r"(b[0]), "r"(b[1]));
}

__device__ __forceinline__ void load_w(char* wb, const float* __restrict__ W, int tid) {
#pragma unroll
    for (int i = 0; i < 16; i++) {
        const int g = i * 256 + tid;
        const int o = g >> 5, f4 = g & 31;
        const float4 v = *reinterpret_cast<const float4*>(W + o * 128 + f4 * 4);
        const uint32_t off = swzW(o, f4 * 4);
        *reinterpret_cast<__half2*>(wb + off)     = __floats2half2_rn(v.x, v.y);
        *reinterpret_cast<__half2*>(wb + off + 4) = __floats2half2_rn(v.z, v.w);
    }
}
__device__ __forceinline__ void pf_load(float4 pf[8], const float* __restrict__ src,
                                        long cstride, int tid) {
#pragma unroll
    for (int i = 0; i < 8; i++) {
        const int g = i * 256 + tid;
        const int c = g >> 4, d4 = (g & 15) * 4;
        pf[i] = *reinterpret_cast<const float4*>(src + (long)c * cstride + d4);
    }
}
__device__ __forceinline__ void pf_store(char* xb, const float4 pf[8], int tid) {
#pragma unroll
    for (int i = 0; i < 8; i++) {
        const int g = i * 256 + tid;
        const int c = g >> 4, d4 = (g & 15) * 4;
        const uint32_t off = swzX(c, d4);
        *reinterpret_cast<__half2*>(xb + off)     = __floats2half2_rn(pf[i].x, pf[i].y);
        *reinterpret_cast<__half2*>(xb + off + 4) = __floats2half2_rn(pf[i].z, pf[i].w);
    }
}

__device__ __forceinline__ void proj(uint32_t wb, uint32_t xb, int warp_m, int warp_n,
                                     int lane, float acc[2][4][4]) {
#pragma unroll
    for (int t = 0; t < 2; t++)
#pragma unroll
        for (int n = 0; n < 4; n++)
#pragma unroll
            for (int i = 0; i < 4; i++) acc[t][n][i] = 0.0f;
#pragma unroll
    for (int ks = 0; ks < 8; ks++) {
        const int c0 = ks * 16;
        uint32_t a[2][4];
#pragma unroll
        for (int t = 0; t < 2; t++) {
            const int row = warp_m * 32 + t * 16 + (lane & 7) + ((lane >> 3) & 1) * 8;
            const int colh = c0 + (lane >> 4) * 8;
            ldsm4(a[t], wb + swzW(row, colh));
        }
        uint32_t bf[4][2];
#pragma unroll
        for (int np = 0; np < 2; np++) {
            const int tl = lane >> 3;
            const int c = c0 + (tl & 1) * 8 + (lane & 7);
            const int d = warp_n * 32 + np * 16 + (tl >> 1) * 8;
            uint32_t r4[4];
            ldsm4t(r4, xb + swzX(c, d));
            bf[np * 2][0] = r4[0]; bf[np * 2][1] = r4[1];
            bf[np * 2 + 1][0] = r4[2]; bf[np * 2 + 1][1] = r4[3];
        }
#pragma unroll
        for (int t = 0; t < 2; t++)
#pragma unroll
            for (int n = 0; n < 4; n++) mma16816(acc[t][n], a[t], bf[n]);
    }
}

// fused K+V projection: one set of B fragments feeds both MMA chains
__device__ __forceinline__ void proj2(uint32_t wbK, uint32_t wbV, uint32_t xb,
                                      int warp_m, int warp_n, int lane,
                                      float kp[2][4][4], float vp[2][4][4]) {
#pragma unroll
    for (int t = 0; t < 2; t++)
#pragma unroll
        for (int n = 0; n < 4; n++)
#pragma unroll
            for (int i = 0; i < 4; i++) { kp[t][n][i] = 0.0f; vp[t][n][i] = 0.0f; }
#pragma unroll
    for (int ks = 0; ks < 8; ks++) {
        const int c0 = ks * 16;
        uint32_t ak[2][4], av[2][4];
#pragma unroll
        for (int t = 0; t < 2; t++) {
            const int row = warp_m * 32 + t * 16 + (lane & 7) + ((lane >> 3) & 1) * 8;
            const int colh = c0 + (lane >> 4) * 8;
            const uint32_t so = swzW(row, colh);
            ldsm4(ak[t], wbK + so);
            ldsm4(av[t], wbV + so);
        }
        uint32_t bf[4][2];
#pragma unroll
        for (int np = 0; np < 2; np++) {
            const int tl = lane >> 3;
            const int c = c0 + (tl & 1) * 8 + (lane & 7);
            const int d = warp_n * 32 + np * 16 + (tl >> 1) * 8;
            uint32_t r4[4];
            ldsm4t(r4, xb + swzX(c, d));
            bf[np * 2][0] = r4[0]; bf[np * 2][1] = r4[1];
            bf[np * 2 + 1][0] = r4[2]; bf[np * 2 + 1][1] = r4[3];
        }
#pragma unroll
        for (int t = 0; t < 2; t++)
#pragma unroll
            for (int n = 0; n < 4; n++) {
                mma16816(kp[t][n], ak[t], bf[n]);
                mma16816(vp[t][n], av[t], bf[n]);
            }
    }
}

__global__ void __launch_bounds__(NT, 1)
deform_attn_hmma(const float* __restrict__ q,  const float* __restrict__ kv,
                 const float* __restrict__ Wq, const float* __restrict__ bq,
                 const float* __restrict__ Wk, const float* __restrict__ Wv,
                 const float* __restrict__ bv, float* __restrict__ out)
{
    extern __shared__ char smem[];
    const uint32_t sb = smem_u32(smem);
    const int tid = threadIdx.x, lane = tid & 31, wid = tid >> 5;
    const int warp_m = wid & 3, warp_n = wid >> 2;
    const int b = blockIdx.y;
    const int dt = blockIdx.x * D_TILE;

    load_w(smem + SM_WQ, Wq, tid);
    load_w(smem + SM_WK, Wk, tid);
    load_w(smem + SM_WV, Wv, tid);
    {
        float4 pf[8];
        pf_load(pf, q + (long)b * Cn * Dn + dt, (long)Dn, tid);
        pf_store(smem + SM_X0, pf, tid);
    }
    __syncthreads();

    // ---- Q projection (stays in registers); bq needed (interacts with kp across s) ----
    float qp[2][4][4];
    proj(sb + SM_WQ, sb + SM_X0, warp_m, warp_n, lane, qp);

    const int r0 = warp_m * 32 + (lane >> 2);
    const float bqr[4] = {bq[r0], bq[r0 + 8], bq[r0 + 16], bq[r0 + 24]};
    const float bvr[4] = {bv[r0], bv[r0 + 8], bv[r0 + 16], bv[r0 + 24]};
#pragma unroll
    for (int t = 0; t < 2; t++)
#pragma unroll
        for (int n = 0; n < 4; n++) {
            qp[t][n][0] += bqr[t * 2];     qp[t][n][1] += bqr[t * 2];
            qp[t][n][2] += bqr[t * 2 + 1]; qp[t][n][3] += bqr[t * 2 + 1];
        }

    float acc[2][4][4], den[2][4][2];
#pragma unroll
    for (int t = 0; t < 2; t++)
#pragma unroll
        for (int n = 0; n < 4; n++) {
            acc[t][n][0] = acc[t][n][1] = acc[t][n][2] = acc[t][n][3] = 0.0f;
            den[t][n][0] = den[t][n][1] = 0.0f;
        }

    __syncthreads();
    {
        float4 pf[8];
        pf_load(pf, kv + (long)(b * Cn) * Sn * Dn + dt, (long)Sn * Dn, tid);
        pf_store(smem + SM_X0, pf, tid);
    }
    __syncthreads();

    float4 pf[8];
    for (int s = 0; s < Sn; s++) {
        const uint32_t xb = sb + ((s & 1) ? SM_X1 : SM_X0);
        if (s + 1 < Sn)
            pf_load(pf, kv + ((long)(b * Cn) * Sn + (s + 1)) * Dn + dt, (long)Sn * Dn, tid);

        float kp[2][4][4], vp[2][4][4];
        proj2(sb + SM_WK, sb + SM_WV, xb, warp_m, warp_n, lane, kp, vp);

#pragma unroll
        for (int t = 0; t < 2; t++)
#pragma unroll
            for (int n = 0; n < 4; n++) {
                float pe = qp[t][n][0] * kp[t][n][0] + qp[t][n][2] * kp[t][n][2];
                float po = qp[t][n][1] * kp[t][n][1] + qp[t][n][3] * kp[t][n][3];
                pe += __shfl_xor_sync(0xffffffffu, pe, 4);
                pe += __shfl_xor_sync(0xffffffffu, pe, 8);
                pe += __shfl_xor_sync(0xffffffffu, pe, 16);
                po += __shfl_xor_sync(0xffffffffu, po, 4);
                po += __shfl_xor_sync(0xffffffffu, po, 8);
                po += __shfl_xor_sync(0xffffffffu, po, 16);
                const float we = __expf(ATT_SCALE * pe);
                const float wo = __expf(ATT_SCALE * po);
                den[t][n][0] += we; den[t][n][1] += wo;
                acc[t][n][0] = fmaf(we, vp[t][n][0], acc[t][n][0]);
                acc[t][n][1] = fmaf(wo, vp[t][n][1], acc[t][n][1]);
                acc[t][n][2] = fmaf(we, vp[t][n][2], acc[t][n][2]);
                acc[t][n][3] = fmaf(wo, vp[t][n][3], acc[t][n][3]);
            }

        __syncthreads();
        if (s + 1 < Sn) {
            pf_store(smem + (((s + 1) & 1) ? SM_X1 : SM_X0), pf, tid);
            __syncthreads();
        }
    }

    // ---- output: out = acc/den + bv ----
#pragma unroll
    for (int t = 0; t < 2; t++)
#pragma unroll
        for (int n = 0; n < 4; n++) {
            const int row = warp_m * 32 + t * 16 + (lane >> 2);
            float* dst = out + ((long)(b * Cn + row)) * Dn + dt + warp_n * 32 + n * 8 + (lane & 3) * 2;
            const float de = den[t][n][0], dz = den[t][n][1];
            float2 v0 = make_float2(acc[t][n][0] / de + bvr[t * 2],
                                    acc[t][n][1] / dz + bvr[t * 2]);
            float2 v1 = make_float2(acc[t][n][2] / de + bvr[t * 2 + 1],
                                    acc[t][n][3] / dz + bvr[t * 2 + 1]);
            *reinterpret_cast<float2*>(dst) = v0;
            *reinterpret_cast<float2*>(dst + (long)8 * Dn) = v1;
        }
}

extern "C" void kernel_launch(void* const* d_in, const int* in_sizes, int n_in,
                              void* d_out, int out_size) {
    const float* q  = (const float*)d_in[0];
    const float* kv = (const float*)d_in[1];
    const float* Wq = (const float*)d_in[2];
    const float* bq = (const float*)d_in[3];
    const float* Wk = (const float*)d_in[4];
    // d_in[5] = bk: unused (softmax-invariant)
    const float* Wv = (const float*)d_in[6];
    const float* bv = (const float*)d_in[7];
    float* out = (float*)d_out;

    cudaFuncSetAttribute(deform_attn_hmma,
                         cudaFuncAttributeMaxDynamicSharedMemorySize, SM_TOTAL);
    dim3 grid(Dn / D_TILE, Bn);   // 256 x 4
    deform_attn_hmma<<<grid, NT, SM_TOTAL>>>(q, kv, Wq, bq, Wk, Wv, bv, out);
}